// round 2
// baseline (speedup 1.0000x reference)
#include <cuda_runtime.h>
#include <cstdint>
#include <cstdio>

// Problem dims (fixed)
#define T_SEQ     2048
#define D_MODEL   2048
#define NH        16
#define DKK       128
#define DVV       128
#define CONV_DIM  6144
#define GEN_HIDDEN 768
#define KERN_N    (CONV_DIM*4)   // 24576

// ---------------- scratch (static __device__, no allocation) ----------------
__device__ float g_qkv [(size_t)T_SEQ*CONV_DIM];   // 50 MB
__device__ float g_h   [(size_t)T_SEQ*GEN_HIDDEN]; // 6 MB
__device__ float g_u   [(size_t)T_SEQ*CONV_DIM];   // 50 MB (conv output)
__device__ float g_beta [T_SEQ*NH];
__device__ float g_decay[T_SEQ*NH];
__device__ float g_qs   [T_SEQ*NH];
__device__ float g_ks   [T_SEQ*NH];
__device__ float g_o   [(size_t)T_SEQ*NH*DVV];     // 16 MB

__device__ __forceinline__ float siluf(float x){ return x / (1.0f + expf(-x)); }

// ---------------- generic tiled SGEMM, 128x128x16, 256 thr, 8x8/thread -----
// MODE 0: C = A@B            (plain)
// MODE 1: C = silu(A@B)
// MODE 2: dynamic-conv epilogue: P = A@B + bias (N=24576), then
//         u[t,d] = silu( sum_w qkv[t+w-3, d] * P[t, 4d+w] ), C has row stride CONV_DIM
template<int MODE>
__global__ __launch_bounds__(256)
void sgemm_kernel(const float* __restrict__ A, const float* __restrict__ B,
                  float* __restrict__ C, int M, int N, int K,
                  const float* __restrict__ bias, const float* __restrict__ qkv_in)
{
    __shared__ float As[16][128];
    __shared__ float Bs[16][128];
    int tid = threadIdx.x;
    int tx = tid & 15, ty = tid >> 4;
    int bm = blockIdx.y * 128, bn = blockIdx.x * 128;

    float acc[8][8];
#pragma unroll
    for (int i=0;i<8;i++)
#pragma unroll
        for (int j=0;j<8;j++) acc[i][j]=0.f;

    int a_row = tid >> 2;          // 0..63
    int a_col = (tid & 3) * 4;     // 0,4,8,12
    int b_row = tid >> 5;          // 0..7
    int b_col = (tid & 31) * 4;    // 0..124

    for (int k0 = 0; k0 < K; k0 += 16) {
#pragma unroll
        for (int r = 0; r < 2; r++) {
            int row = a_row + r*64;
            float4 va = *(const float4*)(A + (size_t)(bm + row)*K + k0 + a_col);
            As[a_col+0][row] = va.x; As[a_col+1][row] = va.y;
            As[a_col+2][row] = va.z; As[a_col+3][row] = va.w;
        }
#pragma unroll
        for (int r = 0; r < 2; r++) {
            int row = b_row + r*8;
            *(float4*)&Bs[row][b_col] = *(const float4*)(B + (size_t)(k0+row)*N + bn + b_col);
        }
        __syncthreads();
#pragma unroll
        for (int kk = 0; kk < 16; kk++) {
            float a[8], b[8];
            *(float4*)&a[0] = *(float4*)&As[kk][ty*8];
            *(float4*)&a[4] = *(float4*)&As[kk][ty*8+4];
            *(float4*)&b[0] = *(float4*)&Bs[kk][tx*8];
            *(float4*)&b[4] = *(float4*)&Bs[kk][tx*8+4];
#pragma unroll
            for (int i=0;i<8;i++)
#pragma unroll
                for (int j=0;j<8;j++) acc[i][j] = fmaf(a[i], b[j], acc[i][j]);
        }
        __syncthreads();
    }

    if (MODE == 0) {
#pragma unroll
        for (int i=0;i<8;i++) {
            float* cp = C + (size_t)(bm + ty*8 + i)*N + bn + tx*8;
            *(float4*)cp     = make_float4(acc[i][0],acc[i][1],acc[i][2],acc[i][3]);
            *(float4*)(cp+4) = make_float4(acc[i][4],acc[i][5],acc[i][6],acc[i][7]);
        }
    } else if (MODE == 1) {
#pragma unroll
        for (int i=0;i<8;i++) {
            float* cp = C + (size_t)(bm + ty*8 + i)*N + bn + tx*8;
            *(float4*)cp     = make_float4(siluf(acc[i][0]),siluf(acc[i][1]),siluf(acc[i][2]),siluf(acc[i][3]));
            *(float4*)(cp+4) = make_float4(siluf(acc[i][4]),siluf(acc[i][5]),siluf(acc[i][6]),siluf(acc[i][7]));
        }
    } else { // MODE 2 : fused dynamic short conv + silu
        int d0 = (bn + tx*8) >> 2;
#pragma unroll
        for (int i=0;i<8;i++) {
            int t = bm + ty*8 + i;
#pragma unroll
            for (int g2=0; g2<2; g2++) {
                int d = d0 + g2;
                float sacc = 0.f;
#pragma unroll
                for (int w=0; w<4; w++) {
                    float kern = acc[i][g2*4+w] + bias[d*4+w];
                    int tsrc = t + w - 3;
                    float uvv = (tsrc >= 0) ? qkv_in[(size_t)tsrc*CONV_DIM + d] : 0.f;
                    sacc = fmaf(uvv, kern, sacc);
                }
                C[(size_t)t*CONV_DIM + d] = siluf(sacc);
            }
        }
    }
}

// ---------------- ba = x @ W_ba  -> beta = sigmoid(b), decay = sigmoid(-a) --
__global__ __launch_bounds__(256)
void ba_kernel(const float* __restrict__ x, const float* __restrict__ W_ba,
               float* __restrict__ beta, float* __restrict__ decay)
{
    int j = threadIdx.x & 31;
    int t = blockIdx.x * 8 + (threadIdx.x >> 5);
    const float* xr = x + (size_t)t * D_MODEL;
    float s = 0.f;
    for (int k = 0; k < D_MODEL; k++) s = fmaf(xr[k], W_ba[k*32 + j], s);
    if (j < 16) beta[t*NH + j]        = 1.0f / (1.0f + expf(-s));
    else        decay[t*NH + (j-16)]  = 1.0f / (1.0f + expf( s)); // exp(-softplus(a))
}

// ---------------- per-(t,h) l2norm scales for q,k ---------------------------
__global__ __launch_bounds__(256)
void scale_kernel(const float* __restrict__ u, float* __restrict__ qs, float* __restrict__ ks)
{
    int gt = blockIdx.x * blockDim.x + threadIdx.x;
    int w = gt >> 5, lane = gt & 31;
    int t = w >> 4, h = w & 15;
    const float* base = u + (size_t)t*CONV_DIM + h*128;
    float4 a = *(const float4*)(base + lane*4);
    float sq = a.x*a.x + a.y*a.y + a.z*a.z + a.w*a.w;
    float4 b = *(const float4*)(base + 2048 + lane*4);
    float sk = b.x*b.x + b.y*b.y + b.z*b.z + b.w*b.w;
#pragma unroll
    for (int m = 16; m >= 1; m >>= 1) {
        sq += __shfl_xor_sync(0xffffffffu, sq, m);
        sk += __shfl_xor_sync(0xffffffffu, sk, m);
    }
    if (lane == 0) {
        qs[t*NH + h] = rsqrtf(sq + 1e-6f) * 0.08838834764831845f; // * DK^-0.5
        ks[t*NH + h] = rsqrtf(sk + 1e-6f);
    }
}

// ---------------- gated delta-rule scan -------------------------------------
// Column-independent recurrence: one block = (head h, 16 v-columns).
// Warp handles 4 columns; 8 lanes/column; lane owns 16 k-slots of S[:,v].
// k,q,v,scalars staged 8 steps ahead with cp.async double buffering.
__device__ __forceinline__ unsigned smem_u32(const void* p){
    return (unsigned)__cvta_generic_to_shared(p);
}
__device__ __forceinline__ void cpa16(const void* s, const void* g){
    asm volatile("cp.async.cg.shared.global [%0], [%1], 16;" :: "r"(smem_u32(s)), "l"(g));
}
__device__ __forceinline__ void cpa4(const void* s, const void* g){
    asm volatile("cp.async.ca.shared.global [%0], [%1], 4;" :: "r"(smem_u32(s)), "l"(g));
}

#define CH 8
#define NCH (T_SEQ/CH)

__global__ __launch_bounds__(128)
void scan_kernel(const float* __restrict__ u,
                 const float* __restrict__ ksc_g, const float* __restrict__ qsc_g,
                 const float* __restrict__ beta_g, const float* __restrict__ decay_g,
                 float* __restrict__ o)
{
    __shared__ float sk[2][CH][128];
    __shared__ float sq[2][CH][128];
    __shared__ float sv[2][CH][16];
    __shared__ float ss[2][CH][4];

    int tid = threadIdx.x, lane = tid & 31, warp = tid >> 5;
    int h = blockIdx.y, vg = blockIdx.x;
    int col_local = warp*4 + (lane >> 3);     // 0..15
    int v = vg*16 + col_local;                // 0..127
    int kg = lane & 7;                        // lane owns k-slots kg*4 + 32*m + {0..3}

    float s[16];
#pragma unroll
    for (int i=0;i<16;i++) s[i] = 0.f;

    auto prefetch = [&](int c, int b){
        int t0 = c*CH;
#pragma unroll
        for (int j2=0;j2<2;j2++){
            int idx = tid + j2*128;
            int st = idx >> 5, f4 = idx & 31;
            const float* rowbase = u + (size_t)(t0+st)*CONV_DIM + h*128 + f4*4;
            cpa16(&sq[b][st][f4*4], rowbase);
            cpa16(&sk[b][st][f4*4], rowbase + 2048);
        }
        if (tid < 32){
            int st = tid >> 2, f4 = tid & 3;
            cpa16(&sv[b][st][f4*4],
                  u + (size_t)(t0+st)*CONV_DIM + 4096 + h*128 + vg*16 + f4*4);
        } else if (tid < 64){
            int r = tid - 32;
            int st = r & 7, wh = r >> 3;
            const float* src = (wh==0) ? ksc_g : (wh==1) ? qsc_g : (wh==2) ? beta_g : decay_g;
            cpa4(&ss[b][st][wh], src + (t0+st)*NH + h);
        }
    };

    prefetch(0, 0);
    asm volatile("cp.async.commit_group;");

    for (int c = 0; c < NCH; c++){
        int b = c & 1;
        if (c+1 < NCH){
            prefetch(c+1, b^1);
            asm volatile("cp.async.commit_group;");
            asm volatile("cp.async.wait_group 1;");
        } else {
            asm volatile("cp.async.wait_group 0;");
        }
        __syncthreads();

#pragma unroll
        for (int j = 0; j < CH; j++){
            float ksc = ss[b][j][0], qsc = ss[b][j][1];
            float bet = ss[b][j][2], eg  = ss[b][j][3];
            float vv  = sv[b][j][col_local];

            float kf[16], qf[16];
#pragma unroll
            for (int m=0;m<4;m++){
                // swizzled k-slot mapping (kg*4 + 32*m): conflict-free LDS.128
                *(float4*)&kf[4*m] = *(const float4*)&sk[b][j][kg*4 + 32*m];
                *(float4*)&qf[4*m] = *(const float4*)&sq[b][j][kg*4 + 32*m];
            }
            // pred = k_hat . (decayed S[:,v])  (scales folded into scalars)
            float a0=0.f, a1=0.f;
#pragma unroll
            for (int i=0;i<16;i+=2){ a0 = fmaf(kf[i], s[i], a0); a1 = fmaf(kf[i+1], s[i+1], a1); }
            float dot = a0 + a1;
            dot += __shfl_xor_sync(0xffffffffu, dot, 1);
            dot += __shfl_xor_sync(0xffffffffu, dot, 2);
            dot += __shfl_xor_sync(0xffffffffu, dot, 4);
            float pred = dot * ksc * eg;
            float uk = bet * (vv - pred) * ksc;   // beta*(v - pred), kscale folded
#pragma unroll
            for (int i=0;i<16;i++) s[i] = fmaf(eg, s[i], kf[i]*uk);
            // o = q_hat . S
            float c0=0.f, c1=0.f;
#pragma unroll
            for (int i=0;i<16;i+=2){ c0 = fmaf(qf[i], s[i], c0); c1 = fmaf(qf[i+1], s[i+1], c1); }
            float od = c0 + c1;
            od += __shfl_xor_sync(0xffffffffu, od, 1);
            od += __shfl_xor_sync(0xffffffffu, od, 2);
            od += __shfl_xor_sync(0xffffffffu, od, 4);
            if (kg == 0){
                int t = c*CH + j;
                o[(size_t)t*(NH*DVV) + h*128 + v] = od * qsc;
            }
        }
        __syncthreads();
    }
}

// ---------------- launch ----------------------------------------------------
extern "C" void kernel_launch(void* const* d_in, const int* in_sizes, int n_in,
                              void* d_out, int out_size)
{
    const float* x      = (const float*)d_in[0];
    const float* W_qkv  = (const float*)d_in[1];
    const float* W_ba   = (const float*)d_in[2];
    const float* gen_w1 = (const float*)d_in[3];
    const float* gen_w2 = (const float*)d_in[4];
    const float* gen_b2 = (const float*)d_in[5];
    const float* W_o    = (const float*)d_in[6];
    float* y = (float*)d_out;

    float *qkv, *h, *u, *beta, *decay, *qs, *ks, *o;
    cudaGetSymbolAddress((void**)&qkv,   g_qkv);
    cudaGetSymbolAddress((void**)&h,     g_h);
    cudaGetSymbolAddress((void**)&u,     g_u);
    cudaGetSymbolAddress((void**)&beta,  g_beta);
    cudaGetSymbolAddress((void**)&decay, g_decay);
    cudaGetSymbolAddress((void**)&qs,    g_qs);
    cudaGetSymbolAddress((void**)&ks,    g_ks);
    cudaGetSymbolAddress((void**)&o,     g_o);

    // 1) qkv = x @ W_qkv                     [2048 x 6144]
    sgemm_kernel<0><<<dim3(CONV_DIM/128, T_SEQ/128), 256>>>(
        x, W_qkv, qkv, T_SEQ, CONV_DIM, D_MODEL, nullptr, nullptr);
    // 2) beta/decay from x @ W_ba
    ba_kernel<<<T_SEQ/8, 256>>>(x, W_ba, beta, decay);
    // 3) h = silu(qkv @ gen_w1)              [2048 x 768]
    sgemm_kernel<1><<<dim3(GEN_HIDDEN/128, T_SEQ/128), 256>>>(
        qkv, gen_w1, h, T_SEQ, GEN_HIDDEN, CONV_DIM, nullptr, nullptr);
    // 4) u = silu(conv(qkv, h@gen_w2 + b2))  [2048 x 6144]  (kern never materialized)
    sgemm_kernel<2><<<dim3(KERN_N/128, T_SEQ/128), 256>>>(
        h, gen_w2, u, T_SEQ, KERN_N, GEN_HIDDEN, gen_b2, qkv);
    // 5) per-(t,h) l2norm scales
    scale_kernel<<<(T_SEQ*NH*32)/256, 256>>>(u, qs, ks);
    // 6) gated delta-rule scan -> o          [2048 x 2048]
    scan_kernel<<<dim3(8, NH), 128>>>(u, ks, qs, beta, decay, o);
    // 7) y = o @ W_o
    sgemm_kernel<0><<<dim3(D_MODEL/128, T_SEQ/128), 256>>>(
        o, W_o, y, T_SEQ, D_MODEL, NH*DVV, nullptr, nullptr);
}

// round 4
// speedup vs baseline: 2.3631x; 2.3631x over previous
#include <cuda_runtime.h>
#include <cuda_bf16.h>
#include <cstdint>

// Problem dims (fixed)
#define T_SEQ     2048
#define D_MODEL   2048
#define NH        16
#define CONV_DIM  6144
#define GEN_HIDDEN 768
#define KERN_N    (CONV_DIM*4)   // 24576

// ---------------- scratch (static __device__, no allocation) ----------------
__device__ float g_qkv [(size_t)T_SEQ*CONV_DIM];
__device__ float g_u   [(size_t)T_SEQ*CONV_DIM];
__device__ float g_o   [(size_t)T_SEQ*D_MODEL];
__device__ float g_beta [T_SEQ*NH];
__device__ float g_decay[T_SEQ*NH];
__device__ float g_qs   [T_SEQ*NH];
__device__ float g_ks   [T_SEQ*NH];

// bf16 hi/lo split activations
__device__ __nv_bfloat16 g_xh  [(size_t)T_SEQ*D_MODEL],   g_xl  [(size_t)T_SEQ*D_MODEL];
__device__ __nv_bfloat16 g_qkvh[(size_t)T_SEQ*CONV_DIM],  g_qkvl[(size_t)T_SEQ*CONV_DIM];
__device__ __nv_bfloat16 g_hh  [(size_t)T_SEQ*GEN_HIDDEN],g_hl  [(size_t)T_SEQ*GEN_HIDDEN];
__device__ __nv_bfloat16 g_oh  [(size_t)T_SEQ*D_MODEL],   g_ol  [(size_t)T_SEQ*D_MODEL];
// bf16 hi/lo split transposed weights ([N,K] K-major)
__device__ __nv_bfloat16 g_wqkvh[(size_t)CONV_DIM*D_MODEL], g_wqkvl[(size_t)CONV_DIM*D_MODEL];
__device__ __nv_bfloat16 g_w1h [(size_t)GEN_HIDDEN*CONV_DIM], g_w1l [(size_t)GEN_HIDDEN*CONV_DIM];
__device__ __nv_bfloat16 g_w2h [(size_t)KERN_N*GEN_HIDDEN],  g_w2l [(size_t)KERN_N*GEN_HIDDEN];
__device__ __nv_bfloat16 g_woh [(size_t)D_MODEL*D_MODEL],    g_wol [(size_t)D_MODEL*D_MODEL];

__device__ __forceinline__ float siluf(float x){ return x / (1.0f + expf(-x)); }

// ---------------- PTX helpers (baseline ISA only: sm_80-level) --------------
__device__ __forceinline__ uint32_t smem_u32(const void* p){
    return (uint32_t)__cvta_generic_to_shared(p);
}
__device__ __forceinline__ void cpa16(uint32_t d, const void* g){
    asm volatile("cp.async.cg.shared.global [%0], [%1], 16;" :: "r"(d), "l"(g));
}
__device__ __forceinline__ void cpa4(const void* s, const void* g){
    asm volatile("cp.async.ca.shared.global [%0], [%1], 4;" :: "r"(smem_u32(s)), "l"(g));
}
__device__ __forceinline__ void cp_commit(){ asm volatile("cp.async.commit_group;" ::: "memory"); }
__device__ __forceinline__ void cp_wait0(){ asm volatile("cp.async.wait_group 0;" ::: "memory"); }
__device__ __forceinline__ void cp_wait1(){ asm volatile("cp.async.wait_group 1;" ::: "memory"); }

__device__ __forceinline__ void ldm_x4(uint32_t* r, uint32_t a){
    asm volatile("ldmatrix.sync.aligned.m8n8.x4.shared.b16 {%0,%1,%2,%3}, [%4];"
        : "=r"(r[0]),"=r"(r[1]),"=r"(r[2]),"=r"(r[3]) : "r"(a));
}
__device__ __forceinline__ void ldm_x2(uint32_t* r, uint32_t a){
    asm volatile("ldmatrix.sync.aligned.m8n8.x2.shared.b16 {%0,%1}, [%2];"
        : "=r"(r[0]),"=r"(r[1]) : "r"(a));
}
__device__ __forceinline__ void mma16816(float* d, const uint32_t* a, const uint32_t* b){
    asm volatile("mma.sync.aligned.m16n8k16.row.col.f32.bf16.bf16.f32 "
        "{%0,%1,%2,%3}, {%4,%5,%6,%7}, {%8,%9}, {%0,%1,%2,%3};"
        : "+f"(d[0]),"+f"(d[1]),"+f"(d[2]),"+f"(d[3])
        : "r"(a[0]),"r"(a[1]),"r"(a[2]),"r"(a[3]), "r"(b[0]),"r"(b[1]));
}

// ---------------- bf16 HMMA GEMM: C[M,N] = A[M,K] @ B_t[N,K]^T --------------
// 3-term split: Ah*Bh + Al*Bh + Ah*Bl, fp32 register accumulators.
// Tile 128x128x32, 256 thr (8 warps 2x4, warp tile 64x32), 3-stage cp.async.
// Smem per stage: Ah(8K) Al(8K) Bh(8K) Bl(8K) = 32KB, 16B-chunk swizzle:
//   phys_chunk = chunk ^ ((row>>1)&3)   (row = 64B)
// MODE 0: C fp32
// MODE 1: C fp32 + Ch/Cl bf16 split        (qkv)
// MODE 2: silu -> Ch/Cl only               (h)
// MODE 3: dynamic-conv epilogue -> C fp32  (u); taps/bias extra inputs
#define STG 32768
#define DSMEM_REQ (3*STG)

template<int MODE>
__global__ __launch_bounds__(256, 2)
void mma_gemm(const __nv_bfloat16* __restrict__ Ah, const __nv_bfloat16* __restrict__ Al,
              const __nv_bfloat16* __restrict__ Bh, const __nv_bfloat16* __restrict__ Bl,
              int N, int K, float* __restrict__ C,
              __nv_bfloat16* __restrict__ Ch, __nv_bfloat16* __restrict__ Cl,
              const float* __restrict__ taps, const float* __restrict__ bias)
{
    extern __shared__ char sm[];
    const int tid = threadIdx.x, lane = tid & 31, wid = tid >> 5;
    const int wm = (wid & 1) * 64, wn = (wid >> 1) * 32;
    const int bm = blockIdx.y * 128, bn = blockIdx.x * 128;
    const int NC = K >> 5;
    const uint32_t smb = smem_u32(sm);

    float acc[4][4][4];
#pragma unroll
    for (int a=0;a<4;a++)
#pragma unroll
    for (int b=0;b<4;b++)
#pragma unroll
    for (int c=0;c<4;c++) acc[a][b][c] = 0.f;

    const __nv_bfloat16* srcs[4] = { Ah + (size_t)bm*K, Al + (size_t)bm*K,
                                     Bh + (size_t)bn*K, Bl + (size_t)bn*K };
    const int ldr = tid >> 2;          // 0..63
    const int ldc = tid & 3;           // 0..3 (16B chunk within 64B row)

    auto prefetch = [&](int ch){
        uint32_t sb = smb + (uint32_t)(ch % 3) * STG;
        int k0 = ch * 32;
#pragma unroll
        for (int i = 0; i < 8; i++){
            const int mat = i >> 1;                 // 0:Ah 1:Al 2:Bh 3:Bl
            const int r = (i & 1) * 64 + ldr;       // 0..127
            uint32_t dst = sb + mat*8192u + (uint32_t)r*64u
                         + ((uint32_t)(ldc ^ ((r >> 1) & 3)) << 4);
            cpa16(dst, srcs[mat] + (size_t)r*K + k0 + ldc*8);
        }
        cp_commit();
    };

    // ldmatrix lane geometry
    const int rA = (lane & 7) + ((lane >> 3) & 1) * 8;   // A row within 16
    const int cA = lane >> 4;                            // A k8-block 0/1
    const int sA = (rA >> 1) & 3;
    const int rB = lane & 7;                             // B row within 8
    const int cB = (lane >> 3) & 1;                      // B k8-block 0/1
    const int sB = (rB >> 1) & 3;

    prefetch(0);
    prefetch(1);

    for (int ch = 0; ch < NC; ch++){
        if (ch + 1 < NC) cp_wait1(); else cp_wait0();
        __syncthreads();
        if (ch + 2 < NC) prefetch(ch + 2);
        uint32_t sb = smb + (uint32_t)(ch % 3) * STG;
#pragma unroll
        for (int kb = 0; kb < 2; kb++){
            uint32_t bhf[4][2], blf[4][2];
#pragma unroll
            for (int nt = 0; nt < 4; nt++){
                int row = wn + nt*8 + rB;
                uint32_t off = (uint32_t)row*64u + ((uint32_t)((kb*2 + cB) ^ sB) << 4);
                ldm_x2(bhf[nt], sb + 16384u + off);
                ldm_x2(blf[nt], sb + 24576u + off);
            }
#pragma unroll
            for (int mt = 0; mt < 4; mt++){
                uint32_t ahf[4], alf[4];
                int row = wm + mt*16 + rA;
                uint32_t off = (uint32_t)row*64u + ((uint32_t)((kb*2 + cA) ^ sA) << 4);
                ldm_x4(ahf, sb + off);
                ldm_x4(alf, sb + 8192u + off);
#pragma unroll
                for (int nt = 0; nt < 4; nt++) mma16816(acc[mt][nt], ahf, bhf[nt]);
#pragma unroll
                for (int nt = 0; nt < 4; nt++) mma16816(acc[mt][nt], alf, bhf[nt]);
#pragma unroll
                for (int nt = 0; nt < 4; nt++) mma16816(acc[mt][nt], ahf, blf[nt]);
            }
        }
    }
    __syncthreads();

    // ------------------ epilogue ------------------
    if (MODE == 3){
        float* staps = (float*)sm;                 // [131][33]
        float* sbias = (float*)(sm + 17424);       // 128 floats
        const int d0g = bn >> 2;                   // 32 d-values per block
        for (int idx = tid; idx < 131*32; idx += 256){
            int i = idx >> 5, dd = idx & 31;
            int t = bm - 3 + i;
            staps[i*33 + dd] = (t >= 0) ? taps[(size_t)t*CONV_DIM + d0g + dd] : 0.f;
        }
        if (tid < 128) sbias[tid] = bias[bn + tid];
        __syncthreads();
#pragma unroll
        for (int mt = 0; mt < 4; mt++)
#pragma unroll
        for (int nt = 0; nt < 4; nt++){
            int cb = wn + nt*8 + (lane & 3)*2;     // kernel-col
            int dd = (cb >> 2) & 31;               // local d
            int w0 = cb & 3;                       // 0 or 2
            float b0 = sbias[cb], b1 = sbias[cb + 1];
#pragma unroll
            for (int rr = 0; rr < 2; rr++){
                int r = wm + mt*16 + (lane >> 2) + rr*8;
                float k0 = acc[mt][nt][rr*2 + 0] + b0;
                float k1 = acc[mt][nt][rr*2 + 1] + b1;
                float part = staps[(r + w0)*33 + dd]*k0 + staps[(r + w0 + 1)*33 + dd]*k1;
                float oth = __shfl_xor_sync(0xffffffffu, part, 1);
                if ((lane & 1) == 0)
                    C[(size_t)(bm + r)*CONV_DIM + d0g + dd] = siluf(part + oth);
            }
        }
    } else {
#pragma unroll
        for (int mt = 0; mt < 4; mt++)
#pragma unroll
        for (int nt = 0; nt < 4; nt++){
            int cb = wn + nt*8 + (lane & 3)*2;
#pragma unroll
            for (int rr = 0; rr < 2; rr++){
                int r = bm + wm + mt*16 + (lane >> 2) + rr*8;
                float v0 = acc[mt][nt][rr*2 + 0], v1 = acc[mt][nt][rr*2 + 1];
                size_t idx = (size_t)r*N + bn + cb;
                if (MODE == 2){ v0 = siluf(v0); v1 = siluf(v1); }
                if (MODE != 2) *(float2*)(C + idx) = make_float2(v0, v1);
                if (MODE >= 1){
                    __nv_bfloat16 h0 = __float2bfloat16(v0), h1 = __float2bfloat16(v1);
                    *(__nv_bfloat162*)(Ch + idx) = __halves2bfloat162(h0, h1);
                    __nv_bfloat16 l0 = __float2bfloat16(v0 - __bfloat162float(h0));
                    __nv_bfloat16 l1 = __float2bfloat16(v1 - __bfloat162float(h1));
                    *(__nv_bfloat162*)(Cl + idx) = __halves2bfloat162(l0, l1);
                }
            }
        }
    }
}

// ---------------- fp32 -> bf16 hi/lo split (row-major) ----------------------
__global__ __launch_bounds__(256)
void split4_kernel(const float* __restrict__ in, __nv_bfloat16* __restrict__ h,
                   __nv_bfloat16* __restrict__ l)
{
    int i = (blockIdx.x*256 + threadIdx.x)*4;
    float4 v = *(const float4*)(in + i);
    __nv_bfloat16 h0=__float2bfloat16(v.x), h1=__float2bfloat16(v.y),
                  h2=__float2bfloat16(v.z), h3=__float2bfloat16(v.w);
    h[i]=h0; h[i+1]=h1; h[i+2]=h2; h[i+3]=h3;
    l[i]  =__float2bfloat16(v.x-__bfloat162float(h0));
    l[i+1]=__float2bfloat16(v.y-__bfloat162float(h1));
    l[i+2]=__float2bfloat16(v.z-__bfloat162float(h2));
    l[i+3]=__float2bfloat16(v.w-__bfloat162float(h3));
}

// ---------------- fp32 [R,C] -> transposed bf16 hi/lo [C,R] -----------------
__global__ __launch_bounds__(256)
void transpose_split_kernel(const float* __restrict__ in, __nv_bfloat16* __restrict__ oh,
                            __nv_bfloat16* __restrict__ ol, int R, int C)
{
    __shared__ float t[32][33];
    int tx = threadIdx.x & 31, ty = threadIdx.x >> 5;   // 32x8
    int rb = blockIdx.y*32, cb = blockIdx.x*32;
#pragma unroll
    for (int j = ty; j < 32; j += 8) t[j][tx] = in[(size_t)(rb+j)*C + cb + tx];
    __syncthreads();
#pragma unroll
    for (int j = ty; j < 32; j += 8){
        float v = t[tx][j];
        size_t idx = (size_t)(cb+j)*R + rb + tx;
        __nv_bfloat16 h = __float2bfloat16(v);
        oh[idx] = h; ol[idx] = __float2bfloat16(v - __bfloat162float(h));
    }
}

// ---------------- ba = x @ W_ba  -> beta = sigmoid(b), decay = sigmoid(-a) --
__global__ __launch_bounds__(256)
void ba_kernel(const float* __restrict__ x, const float* __restrict__ W_ba,
               float* __restrict__ beta, float* __restrict__ decay)
{
    int j = threadIdx.x & 31;
    int t = blockIdx.x * 8 + (threadIdx.x >> 5);
    const float* xr = x + (size_t)t * D_MODEL;
    float s = 0.f;
    for (int k = 0; k < D_MODEL; k++) s = fmaf(xr[k], W_ba[k*32 + j], s);
    if (j < 16) beta[t*NH + j]        = 1.0f / (1.0f + expf(-s));
    else        decay[t*NH + (j-16)]  = 1.0f / (1.0f + expf( s));
}

// ---------------- per-(t,h) l2norm scales for q,k ---------------------------
__global__ __launch_bounds__(256)
void scale_kernel(const float* __restrict__ u, float* __restrict__ qs, float* __restrict__ ks)
{
    int gt = blockIdx.x * blockDim.x + threadIdx.x;
    int w = gt >> 5, lane = gt & 31;
    int t = w >> 4, h = w & 15;
    const float* base = u + (size_t)t*CONV_DIM + h*128;
    float4 a = *(const float4*)(base + lane*4);
    float sq = a.x*a.x + a.y*a.y + a.z*a.z + a.w*a.w;
    float4 b = *(const float4*)(base + 2048 + lane*4);
    float sk = b.x*b.x + b.y*b.y + b.z*b.z + b.w*b.w;
#pragma unroll
    for (int m = 16; m >= 1; m >>= 1) {
        sq += __shfl_xor_sync(0xffffffffu, sq, m);
        sk += __shfl_xor_sync(0xffffffffu, sk, m);
    }
    if (lane == 0) {
        qs[t*NH + h] = rsqrtf(sq + 1e-6f) * 0.08838834764831845f;
        ks[t*NH + h] = rsqrtf(sk + 1e-6f);
    }
}

// ---------------- gated delta-rule scan (unchanged from R1 pass) ------------
#define CH 8
#define NCH (T_SEQ/CH)

__global__ __launch_bounds__(128)
void scan_kernel(const float* __restrict__ u,
                 const float* __restrict__ ksc_g, const float* __restrict__ qsc_g,
                 const float* __restrict__ beta_g, const float* __restrict__ decay_g,
                 float* __restrict__ o)
{
    __shared__ float sk[2][CH][128];
    __shared__ float sq[2][CH][128];
    __shared__ float sv[2][CH][16];
    __shared__ float ss[2][CH][4];

    int tid = threadIdx.x, lane = tid & 31, warp = tid >> 5;
    int h = blockIdx.y, vg = blockIdx.x;
    int col_local = warp*4 + (lane >> 3);
    int v = vg*16 + col_local;
    int kg = lane & 7;

    float s[16];
#pragma unroll
    for (int i=0;i<16;i++) s[i] = 0.f;

    auto prefetch = [&](int c, int b){
        int t0 = c*CH;
#pragma unroll
        for (int j2=0;j2<2;j2++){
            int idx = tid + j2*128;
            int st = idx >> 5, f4 = idx & 31;
            const float* rowbase = u + (size_t)(t0+st)*CONV_DIM + h*128 + f4*4;
            cpa16(smem_u32(&sq[b][st][f4*4]), rowbase);
            cpa16(smem_u32(&sk[b][st][f4*4]), rowbase + 2048);
        }
        if (tid < 32){
            int st = tid >> 2, f4 = tid & 3;
            cpa16(smem_u32(&sv[b][st][f4*4]),
                  u + (size_t)(t0+st)*CONV_DIM + 4096 + h*128 + vg*16 + f4*4);
        } else if (tid < 64){
            int r = tid - 32;
            int st = r & 7, wh = r >> 3;
            const float* src = (wh==0) ? ksc_g : (wh==1) ? qsc_g : (wh==2) ? beta_g : decay_g;
            cpa4(&ss[b][st][wh], src + (t0+st)*NH + h);
        }
    };

    prefetch(0, 0);
    cp_commit();

    for (int c = 0; c < NCH; c++){
        int b = c & 1;
        if (c+1 < NCH){
            prefetch(c+1, b^1);
            cp_commit();
            cp_wait1();
        } else {
            cp_wait0();
        }
        __syncthreads();

#pragma unroll
        for (int j = 0; j < CH; j++){
            float ksc = ss[b][j][0], qsc = ss[b][j][1];
            float bet = ss[b][j][2], eg  = ss[b][j][3];
            float vv  = sv[b][j][col_local];

            float kf[16], qf[16];
#pragma unroll
            for (int m=0;m<4;m++){
                *(float4*)&kf[4*m] = *(const float4*)&sk[b][j][kg*4 + 32*m];
                *(float4*)&qf[4*m] = *(const float4*)&sq[b][j][kg*4 + 32*m];
            }
            float a0=0.f, a1=0.f;
#pragma unroll
            for (int i=0;i<16;i+=2){ a0 = fmaf(kf[i], s[i], a0); a1 = fmaf(kf[i+1], s[i+1], a1); }
            float dot = a0 + a1;
            dot += __shfl_xor_sync(0xffffffffu, dot, 1);
            dot += __shfl_xor_sync(0xffffffffu, dot, 2);
            dot += __shfl_xor_sync(0xffffffffu, dot, 4);
            float pred = dot * ksc * eg;
            float uk = bet * (vv - pred) * ksc;
#pragma unroll
            for (int i=0;i<16;i++) s[i] = fmaf(eg, s[i], kf[i]*uk);
            float c0=0.f, c1=0.f;
#pragma unroll
            for (int i=0;i<16;i+=2){ c0 = fmaf(qf[i], s[i], c0); c1 = fmaf(qf[i+1], s[i+1], c1); }
            float od = c0 + c1;
            od += __shfl_xor_sync(0xffffffffu, od, 1);
            od += __shfl_xor_sync(0xffffffffu, od, 2);
            od += __shfl_xor_sync(0xffffffffu, od, 4);
            if (kg == 0){
                int t = c*CH + j;
                o[(size_t)t*(NH*128) + h*128 + v] = od * qsc;
            }
        }
        __syncthreads();
    }
}

// ---------------- launch ----------------------------------------------------
extern "C" void kernel_launch(void* const* d_in, const int* in_sizes, int n_in,
                              void* d_out, int out_size)
{
    const float* x      = (const float*)d_in[0];
    const float* W_qkv  = (const float*)d_in[1];
    const float* W_ba   = (const float*)d_in[2];
    const float* gen_w1 = (const float*)d_in[3];
    const float* gen_w2 = (const float*)d_in[4];
    const float* gen_b2 = (const float*)d_in[5];
    const float* W_o    = (const float*)d_in[6];
    float* y = (float*)d_out;

    float *qkv, *u, *o, *beta, *decay, *qs, *ks;
    cudaGetSymbolAddress((void**)&qkv,   g_qkv);
    cudaGetSymbolAddress((void**)&u,     g_u);
    cudaGetSymbolAddress((void**)&o,     g_o);
    cudaGetSymbolAddress((void**)&beta,  g_beta);
    cudaGetSymbolAddress((void**)&decay, g_decay);
    cudaGetSymbolAddress((void**)&qs,    g_qs);
    cudaGetSymbolAddress((void**)&ks,    g_ks);
    __nv_bfloat16 *xh,*xl,*qkvh,*qkvl,*hh,*hl,*oh,*ol;
    __nv_bfloat16 *wqkvh,*wqkvl,*w1h,*w1l,*w2h,*w2l,*woh,*wol;
    cudaGetSymbolAddress((void**)&xh, g_xh);     cudaGetSymbolAddress((void**)&xl, g_xl);
    cudaGetSymbolAddress((void**)&qkvh, g_qkvh); cudaGetSymbolAddress((void**)&qkvl, g_qkvl);
    cudaGetSymbolAddress((void**)&hh, g_hh);     cudaGetSymbolAddress((void**)&hl, g_hl);
    cudaGetSymbolAddress((void**)&oh, g_oh);     cudaGetSymbolAddress((void**)&ol, g_ol);
    cudaGetSymbolAddress((void**)&wqkvh, g_wqkvh); cudaGetSymbolAddress((void**)&wqkvl, g_wqkvl);
    cudaGetSymbolAddress((void**)&w1h, g_w1h);   cudaGetSymbolAddress((void**)&w1l, g_w1l);
    cudaGetSymbolAddress((void**)&w2h, g_w2h);   cudaGetSymbolAddress((void**)&w2l, g_w2l);
    cudaGetSymbolAddress((void**)&woh, g_woh);   cudaGetSymbolAddress((void**)&wol, g_wol);

    cudaFuncSetAttribute(mma_gemm<0>, cudaFuncAttributeMaxDynamicSharedMemorySize, DSMEM_REQ);
    cudaFuncSetAttribute(mma_gemm<1>, cudaFuncAttributeMaxDynamicSharedMemorySize, DSMEM_REQ);
    cudaFuncSetAttribute(mma_gemm<2>, cudaFuncAttributeMaxDynamicSharedMemorySize, DSMEM_REQ);
    cudaFuncSetAttribute(mma_gemm<3>, cudaFuncAttributeMaxDynamicSharedMemorySize, DSMEM_REQ);

    // weight transpose+split  ([K,N] fp32 -> [N,K] bf16 hi/lo)
    transpose_split_kernel<<<dim3(CONV_DIM/32, D_MODEL/32), 256>>>(W_qkv, wqkvh, wqkvl, D_MODEL, CONV_DIM);
    transpose_split_kernel<<<dim3(GEN_HIDDEN/32, CONV_DIM/32), 256>>>(gen_w1, w1h, w1l, CONV_DIM, GEN_HIDDEN);
    transpose_split_kernel<<<dim3(KERN_N/32, GEN_HIDDEN/32), 256>>>(gen_w2, w2h, w2l, GEN_HIDDEN, KERN_N);
    transpose_split_kernel<<<dim3(D_MODEL/32, D_MODEL/32), 256>>>(W_o, woh, wol, D_MODEL, D_MODEL);
    // x split
    split4_kernel<<<(T_SEQ*D_MODEL)/1024, 256>>>(x, xh, xl);
    // beta / decay
    ba_kernel<<<T_SEQ/8, 256>>>(x, W_ba, beta, decay);

    // 1) qkv = x @ W_qkv  (fp32 + bf16 split outputs)
    mma_gemm<1><<<dim3(CONV_DIM/128, T_SEQ/128), 256, DSMEM_REQ>>>(
        xh, xl, wqkvh, wqkvl, CONV_DIM, D_MODEL, qkv, qkvh, qkvl, nullptr, nullptr);
    // 2) h = silu(qkv @ gen_w1)  (bf16 split only)
    mma_gemm<2><<<dim3(GEN_HIDDEN/128, T_SEQ/128), 256, DSMEM_REQ>>>(
        qkvh, qkvl, w1h, w1l, GEN_HIDDEN, CONV_DIM, nullptr, hh, hl, nullptr, nullptr);
    // 3) u = silu(conv(qkv, h @ gen_w2 + b2))  (fused conv epilogue)
    mma_gemm<3><<<dim3(KERN_N/128, T_SEQ/128), 256, DSMEM_REQ>>>(
        hh, hl, w2h, w2l, KERN_N, GEN_HIDDEN, u, nullptr, nullptr, qkv, gen_b2);
    // 4) scales + scan
    scale_kernel<<<(T_SEQ*NH*32)/256, 256>>>(u, qs, ks);
    scan_kernel<<<dim3(8, NH), 128>>>(u, ks, qs, beta, decay, o);
    // 5) o split + y = o @ W_o
    split4_kernel<<<(T_SEQ*D_MODEL)/1024, 256>>>(o, oh, ol);
    mma_gemm<0><<<dim3(D_MODEL/128, T_SEQ/128), 256, DSMEM_REQ>>>(
        oh, ol, woh, wol, D_MODEL, D_MODEL, y, nullptr, nullptr, nullptr, nullptr);
}

// round 5
// speedup vs baseline: 2.3761x; 1.0055x over previous
#include <cuda_runtime.h>
#include <cuda_bf16.h>
#include <cstdint>

// Problem dims (fixed)
#define T_SEQ     2048
#define D_MODEL   2048
#define NH        16
#define CONV_DIM  6144
#define GEN_HIDDEN 768
#define KERN_N    (CONV_DIM*4)   // 24576

// ---------------- scratch (static __device__, no allocation) ----------------
__device__ float g_qkv [(size_t)T_SEQ*CONV_DIM];
__device__ float g_u   [(size_t)T_SEQ*CONV_DIM];
__device__ float g_o   [(size_t)T_SEQ*D_MODEL];
__device__ float g_beta [T_SEQ*NH];
__device__ float g_decay[T_SEQ*NH];
__device__ float g_qs   [T_SEQ*NH];
__device__ float g_ks   [T_SEQ*NH];

// bf16 hi/lo split activations
__device__ __nv_bfloat16 g_xh  [(size_t)T_SEQ*D_MODEL],   g_xl  [(size_t)T_SEQ*D_MODEL];
__device__ __nv_bfloat16 g_qkvh[(size_t)T_SEQ*CONV_DIM],  g_qkvl[(size_t)T_SEQ*CONV_DIM];
__device__ __nv_bfloat16 g_hh  [(size_t)T_SEQ*GEN_HIDDEN],g_hl  [(size_t)T_SEQ*GEN_HIDDEN];
__device__ __nv_bfloat16 g_oh  [(size_t)T_SEQ*D_MODEL],   g_ol  [(size_t)T_SEQ*D_MODEL];
// bf16 hi/lo split transposed weights ([N,K] K-major)
__device__ __nv_bfloat16 g_wqkvh[(size_t)CONV_DIM*D_MODEL], g_wqkvl[(size_t)CONV_DIM*D_MODEL];
__device__ __nv_bfloat16 g_w1h [(size_t)GEN_HIDDEN*CONV_DIM], g_w1l [(size_t)GEN_HIDDEN*CONV_DIM];
__device__ __nv_bfloat16 g_w2h [(size_t)KERN_N*GEN_HIDDEN],  g_w2l [(size_t)KERN_N*GEN_HIDDEN];
__device__ __nv_bfloat16 g_woh [(size_t)D_MODEL*D_MODEL],    g_wol [(size_t)D_MODEL*D_MODEL];

__device__ __forceinline__ float siluf(float x){ return x / (1.0f + expf(-x)); }

// ---------------- PTX helpers (baseline ISA only: sm_80-level) --------------
__device__ __forceinline__ uint32_t smem_u32(const void* p){
    return (uint32_t)__cvta_generic_to_shared(p);
}
__device__ __forceinline__ void cpa16(uint32_t d, const void* g){
    asm volatile("cp.async.cg.shared.global [%0], [%1], 16;" :: "r"(d), "l"(g));
}
__device__ __forceinline__ void cpa4(const void* s, const void* g){
    asm volatile("cp.async.ca.shared.global [%0], [%1], 4;" :: "r"(smem_u32(s)), "l"(g));
}
__device__ __forceinline__ void cp_commit(){ asm volatile("cp.async.commit_group;" ::: "memory"); }
__device__ __forceinline__ void cp_wait0(){ asm volatile("cp.async.wait_group 0;" ::: "memory"); }
__device__ __forceinline__ void cp_wait1(){ asm volatile("cp.async.wait_group 1;" ::: "memory"); }

__device__ __forceinline__ void ldm_x4(uint32_t* r, uint32_t a){
    asm volatile("ldmatrix.sync.aligned.m8n8.x4.shared.b16 {%0,%1,%2,%3}, [%4];"
        : "=r"(r[0]),"=r"(r[1]),"=r"(r[2]),"=r"(r[3]) : "r"(a));
}
__device__ __forceinline__ void mma16816(float* d, const uint32_t* a, const uint32_t* b){
    asm volatile("mma.sync.aligned.m16n8k16.row.col.f32.bf16.bf16.f32 "
        "{%0,%1,%2,%3}, {%4,%5,%6,%7}, {%8,%9}, {%0,%1,%2,%3};"
        : "+f"(d[0]),"+f"(d[1]),"+f"(d[2]),"+f"(d[3])
        : "r"(a[0]),"r"(a[1]),"r"(a[2]),"r"(a[3]), "r"(b[0]),"r"(b[1]));
}

// ---------------- bf16 HMMA GEMM: C[M,N] = A[M,K] @ B_t[N,K]^T --------------
// 3-term split: Ah*Bh + Al*Bh + Ah*Bl, fp32 register accumulators.
// Tile 128xBN x32, 256 thr, 3-stage cp.async, swizzled smem:
//   phys_chunk16 = chunk ^ ((row>>1)&3)   (row = 64B)
// BN=128: 8 warps 2x4 (warp 64x32, MT=4).  BN=64: 8 warps 4x2 (warp 32x32, MT=2).
// B operands via ldmatrix x4 (4 8x8 mats per issue); A double-buffered over (kb,mt).
// MODE 0: C fp32
// MODE 1: C fp32 + Ch/Cl bf16 split        (qkv)
// MODE 2: silu -> Ch/Cl only               (h)
// MODE 3: dynamic-conv epilogue -> C fp32  (u); taps/bias extra inputs

template<int MODE, int BN>
__global__ __launch_bounds__(256, 2)
void mma_gemm(const __nv_bfloat16* __restrict__ Ah, const __nv_bfloat16* __restrict__ Al,
              const __nv_bfloat16* __restrict__ Bh, const __nv_bfloat16* __restrict__ Bl,
              int N, int K, float* __restrict__ C,
              __nv_bfloat16* __restrict__ Ch, __nv_bfloat16* __restrict__ Cl,
              const float* __restrict__ taps, const float* __restrict__ bias)
{
    constexpr int MT  = (BN == 128) ? 4 : 2;
    constexpr int STG = 16384 + BN*128;        // Ah+Al (16K) + Bh+Bl
    extern __shared__ char sm[];
    const int tid = threadIdx.x, lane = tid & 31, wid = tid >> 5;
    const int wm = (BN == 128) ? ((wid & 1) * 64) : ((wid & 3) * 32);
    const int wn = (BN == 128) ? ((wid >> 1) * 32) : ((wid >> 2) * 32);
    const int bm = blockIdx.y * 128, bn = blockIdx.x * BN;
    const int NC = K >> 5;
    const uint32_t smb = smem_u32(sm);

    float acc[MT][4][4];
#pragma unroll
    for (int a=0;a<MT;a++)
#pragma unroll
    for (int b=0;b<4;b++)
#pragma unroll
    for (int c=0;c<4;c++) acc[a][b][c] = 0.f;

    const __nv_bfloat16* srcs[4] = { Ah + (size_t)bm*K, Al + (size_t)bm*K,
                                     Bh + (size_t)bn*K, Bl + (size_t)bn*K };
    const int ldr = tid >> 2;          // 0..63
    const int ldc = tid & 3;           // 16B chunk within 64B row

    auto prefetch = [&](int ch){
        uint32_t sb = smb + (uint32_t)(ch % 3) * STG;
        int k0 = ch * 32;
#pragma unroll
        for (int i = 0; i < 4; i++){                       // A: Ah/Al, 128 rows
            int r = ldr + (i & 1) * 64;
            int mat = i >> 1;
            cpa16(sb + mat*8192u + (uint32_t)r*64u + ((uint32_t)(ldc ^ ((r >> 1) & 3)) << 4),
                  srcs[mat] + (size_t)r*K + k0 + ldc*8);
        }
        if (BN == 128){
#pragma unroll
            for (int i = 0; i < 4; i++){
                int r = ldr + (i & 1) * 64;
                int m = i >> 1;
                cpa16(sb + 16384u + m*8192u + (uint32_t)r*64u + ((uint32_t)(ldc ^ ((r >> 1) & 3)) << 4),
                      srcs[2 + m] + (size_t)r*K + k0 + ldc*8);
            }
        } else {
#pragma unroll
            for (int i = 0; i < 2; i++){
                int r = ldr;
                cpa16(sb + 16384u + i*(uint32_t)(BN*64) + (uint32_t)r*64u + ((uint32_t)(ldc ^ ((r >> 1) & 3)) << 4),
                      srcs[2 + i] + (size_t)r*K + k0 + ldc*8);
            }
        }
        cp_commit();
    };

    // ldmatrix lane geometry
    const int rA = (lane & 7) + ((lane >> 3) & 1) * 8;   // A row within 16
    const int cA = lane >> 4;                            // A k8-half 0/1
    const int jB = lane >> 3;                            // x4 matrix index
    const int ntOff = jB >> 1;                           // nt within pair
    const int cBn = jB & 1;                              // k8-half
    const int rBn = lane & 7;

    prefetch(0);
    prefetch(1);

    for (int ch = 0; ch < NC; ch++){
        if (ch + 1 < NC) cp_wait1(); else cp_wait0();
        __syncthreads();
        uint32_t sb  = smb + (uint32_t)(ch % 3) * STG;
        uint32_t sbB = sb + 16384u;

        uint32_t bh[4][2], bl[4][2];
        uint32_t ah[2][4], al[2][4];

        auto loadB = [&](int kb){
#pragma unroll
            for (int p = 0; p < 2; p++){
                int nt = p*2 + ntOff;
                int row = wn + nt*8 + rBn;
                uint32_t off = (uint32_t)row*64u + ((uint32_t)((kb*2 + cBn) ^ ((row >> 1) & 3)) << 4);
                uint32_t t[4];
                ldm_x4(t, sbB + off);
                bh[p*2][0]=t[0]; bh[p*2][1]=t[1]; bh[p*2+1][0]=t[2]; bh[p*2+1][1]=t[3];
                ldm_x4(t, sbB + (uint32_t)(BN*64) + off);
                bl[p*2][0]=t[0]; bl[p*2][1]=t[1]; bl[p*2+1][0]=t[2]; bl[p*2+1][1]=t[3];
            }
        };
        auto loadA = [&](int kb, int mt, int buf){
            int row = wm + mt*16 + rA;
            uint32_t off = (uint32_t)row*64u + ((uint32_t)((kb*2 + cA) ^ ((row >> 1) & 3)) << 4);
            ldm_x4(ah[buf], sb + off);
            ldm_x4(al[buf], sb + 8192u + off);
        };

        loadB(0);
        loadA(0, 0, 0);
        if (ch + 2 < NC) prefetch(ch + 2);

#pragma unroll
        for (int kb = 0; kb < 2; kb++){
#pragma unroll
            for (int mt = 0; mt < MT; mt++){
                int buf = (kb*MT + mt) & 1;
                if (mt + 1 < MT)      loadA(kb, mt + 1, buf ^ 1);
                else if (kb == 0)     loadA(1, 0, buf ^ 1);
#pragma unroll
                for (int nt = 0; nt < 4; nt++) mma16816(acc[mt][nt], ah[buf], bh[nt]);
#pragma unroll
                for (int nt = 0; nt < 4; nt++) mma16816(acc[mt][nt], al[buf], bh[nt]);
#pragma unroll
                for (int nt = 0; nt < 4; nt++) mma16816(acc[mt][nt], ah[buf], bl[nt]);
                if (kb == 0 && mt == MT - 1) loadB(1);
            }
        }
    }
    __syncthreads();

    // ------------------ epilogue ------------------
    if (MODE == 3){
        float* staps = (float*)sm;                 // [131][33]
        float* sbias = (float*)(sm + 17424);       // 128 floats
        const int d0g = bn >> 2;                   // 32 d-values per block
        for (int idx = tid; idx < 131*32; idx += 256){
            int i = idx >> 5, dd = idx & 31;
            int t = bm - 3 + i;
            staps[i*33 + dd] = (t >= 0) ? taps[(size_t)t*CONV_DIM + d0g + dd] : 0.f;
        }
        if (tid < 128) sbias[tid] = bias[bn + tid];
        __syncthreads();
#pragma unroll
        for (int mt = 0; mt < MT; mt++)
#pragma unroll
        for (int nt = 0; nt < 4; nt++){
            int cb = wn + nt*8 + (lane & 3)*2;     // kernel-col
            int dd = (cb >> 2) & 31;               // local d
            int w0 = cb & 3;                       // 0 or 2
            float b0 = sbias[cb], b1 = sbias[cb + 1];
#pragma unroll
            for (int rr = 0; rr < 2; rr++){
                int r = wm + mt*16 + (lane >> 2) + rr*8;
                float k0 = acc[mt][nt][rr*2 + 0] + b0;
                float k1 = acc[mt][nt][rr*2 + 1] + b1;
                float part = staps[(r + w0)*33 + dd]*k0 + staps[(r + w0 + 1)*33 + dd]*k1;
                float oth = __shfl_xor_sync(0xffffffffu, part, 1);
                if ((lane & 1) == 0)
                    C[(size_t)(bm + r)*CONV_DIM + d0g + dd] = siluf(part + oth);
            }
        }
    } else {
#pragma unroll
        for (int mt = 0; mt < MT; mt++)
#pragma unroll
        for (int nt = 0; nt < 4; nt++){
            int cb = wn + nt*8 + (lane & 3)*2;
#pragma unroll
            for (int rr = 0; rr < 2; rr++){
                int r = bm + wm + mt*16 + (lane >> 2) + rr*8;
                float v0 = acc[mt][nt][rr*2 + 0], v1 = acc[mt][nt][rr*2 + 1];
                size_t idx = (size_t)r*N + bn + cb;
                if (MODE == 2){ v0 = siluf(v0); v1 = siluf(v1); }
                if (MODE != 2) *(float2*)(C + idx) = make_float2(v0, v1);
                if (MODE >= 1){
                    __nv_bfloat16 h0 = __float2bfloat16(v0), h1 = __float2bfloat16(v1);
                    *(__nv_bfloat162*)(Ch + idx) = __halves2bfloat162(h0, h1);
                    __nv_bfloat16 l0 = __float2bfloat16(v0 - __bfloat162float(h0));
                    __nv_bfloat16 l1 = __float2bfloat16(v1 - __bfloat162float(h1));
                    *(__nv_bfloat162*)(Cl + idx) = __halves2bfloat162(l0, l1);
                }
            }
        }
    }
}

// ---------------- fp32 -> bf16 hi/lo split (row-major) ----------------------
__global__ __launch_bounds__(256)
void split4_kernel(const float* __restrict__ in, __nv_bfloat16* __restrict__ h,
                   __nv_bfloat16* __restrict__ l)
{
    int i = (blockIdx.x*256 + threadIdx.x)*4;
    float4 v = *(const float4*)(in + i);
    __nv_bfloat16 h0=__float2bfloat16(v.x), h1=__float2bfloat16(v.y),
                  h2=__float2bfloat16(v.z), h3=__float2bfloat16(v.w);
    h[i]=h0; h[i+1]=h1; h[i+2]=h2; h[i+3]=h3;
    l[i]  =__float2bfloat16(v.x-__bfloat162float(h0));
    l[i+1]=__float2bfloat16(v.y-__bfloat162float(h1));
    l[i+2]=__float2bfloat16(v.z-__bfloat162float(h2));
    l[i+3]=__float2bfloat16(v.w-__bfloat162float(h3));
}

// ---------------- fp32 [R,C] -> transposed bf16 hi/lo [C,R] -----------------
__global__ __launch_bounds__(256)
void transpose_split_kernel(const float* __restrict__ in, __nv_bfloat16* __restrict__ oh,
                            __nv_bfloat16* __restrict__ ol, int R, int C)
{
    __shared__ float t[32][33];
    int tx = threadIdx.x & 31, ty = threadIdx.x >> 5;   // 32x8
    int rb = blockIdx.y*32, cb = blockIdx.x*32;
#pragma unroll
    for (int j = ty; j < 32; j += 8) t[j][tx] = in[(size_t)(rb+j)*C + cb + tx];
    __syncthreads();
#pragma unroll
    for (int j = ty; j < 32; j += 8){
        float v = t[tx][j];
        size_t idx = (size_t)(cb+j)*R + rb + tx;
        __nv_bfloat16 h = __float2bfloat16(v);
        oh[idx] = h; ol[idx] = __float2bfloat16(v - __bfloat162float(h));
    }
}

// ---------------- ba = x @ W_ba  -> beta = sigmoid(b), decay = sigmoid(-a) --
__global__ __launch_bounds__(256)
void ba_kernel(const float* __restrict__ x, const float* __restrict__ W_ba,
               float* __restrict__ beta, float* __restrict__ decay)
{
    int j = threadIdx.x & 31;
    int t = blockIdx.x * 8 + (threadIdx.x >> 5);
    const float* xr = x + (size_t)t * D_MODEL;
    float s = 0.f;
    for (int k = 0; k < D_MODEL; k++) s = fmaf(xr[k], W_ba[k*32 + j], s);
    if (j < 16) beta[t*NH + j]        = 1.0f / (1.0f + expf(-s));
    else        decay[t*NH + (j-16)]  = 1.0f / (1.0f + expf( s));
}

// ---------------- per-(t,h) l2norm scales for q,k ---------------------------
__global__ __launch_bounds__(256)
void scale_kernel(const float* __restrict__ u, float* __restrict__ qs, float* __restrict__ ks)
{
    int gt = blockIdx.x * blockDim.x + threadIdx.x;
    int w = gt >> 5, lane = gt & 31;
    int t = w >> 4, h = w & 15;
    const float* base = u + (size_t)t*CONV_DIM + h*128;
    float4 a = *(const float4*)(base + lane*4);
    float sq = a.x*a.x + a.y*a.y + a.z*a.z + a.w*a.w;
    float4 b = *(const float4*)(base + 2048 + lane*4);
    float sk = b.x*b.x + b.y*b.y + b.z*b.z + b.w*b.w;
#pragma unroll
    for (int m = 16; m >= 1; m >>= 1) {
        sq += __shfl_xor_sync(0xffffffffu, sq, m);
        sk += __shfl_xor_sync(0xffffffffu, sk, m);
    }
    if (lane == 0) {
        qs[t*NH + h] = rsqrtf(sq + 1e-6f) * 0.08838834764831845f;
        ks[t*NH + h] = rsqrtf(sk + 1e-6f);
    }
}

// ---------------- gated delta-rule scan (unchanged, proven) -----------------
#define CH 8
#define NCH (T_SEQ/CH)

__global__ __launch_bounds__(128)
void scan_kernel(const float* __restrict__ u,
                 const float* __restrict__ ksc_g, const float* __restrict__ qsc_g,
                 const float* __restrict__ beta_g, const float* __restrict__ decay_g,
                 float* __restrict__ o)
{
    __shared__ float sk[2][CH][128];
    __shared__ float sq[2][CH][128];
    __shared__ float sv[2][CH][16];
    __shared__ float ss[2][CH][4];

    int tid = threadIdx.x, lane = tid & 31, warp = tid >> 5;
    int h = blockIdx.y, vg = blockIdx.x;
    int col_local = warp*4 + (lane >> 3);
    int v = vg*16 + col_local;
    int kg = lane & 7;

    float s[16];
#pragma unroll
    for (int i=0;i<16;i++) s[i] = 0.f;

    auto prefetch = [&](int c, int b){
        int t0 = c*CH;
#pragma unroll
        for (int j2=0;j2<2;j2++){
            int idx = tid + j2*128;
            int st = idx >> 5, f4 = idx & 31;
            const float* rowbase = u + (size_t)(t0+st)*CONV_DIM + h*128 + f4*4;
            cpa16(smem_u32(&sq[b][st][f4*4]), rowbase);
            cpa16(smem_u32(&sk[b][st][f4*4]), rowbase + 2048);
        }
        if (tid < 32){
            int st = tid >> 2, f4 = tid & 3;
            cpa16(smem_u32(&sv[b][st][f4*4]),
                  u + (size_t)(t0+st)*CONV_DIM + 4096 + h*128 + vg*16 + f4*4);
        } else if (tid < 64){
            int r = tid - 32;
            int st = r & 7, wh = r >> 3;
            const float* src = (wh==0) ? ksc_g : (wh==1) ? qsc_g : (wh==2) ? beta_g : decay_g;
            cpa4(&ss[b][st][wh], src + (t0+st)*NH + h);
        }
    };

    prefetch(0, 0);
    cp_commit();

    for (int c = 0; c < NCH; c++){
        int b = c & 1;
        if (c+1 < NCH){
            prefetch(c+1, b^1);
            cp_commit();
            cp_wait1();
        } else {
            cp_wait0();
        }
        __syncthreads();

#pragma unroll
        for (int j = 0; j < CH; j++){
            float ksc = ss[b][j][0], qsc = ss[b][j][1];
            float bet = ss[b][j][2], eg  = ss[b][j][3];
            float vv  = sv[b][j][col_local];

            float kf[16], qf[16];
#pragma unroll
            for (int m=0;m<4;m++){
                *(float4*)&kf[4*m] = *(const float4*)&sk[b][j][kg*4 + 32*m];
                *(float4*)&qf[4*m] = *(const float4*)&sq[b][j][kg*4 + 32*m];
            }
            float a0=0.f, a1=0.f;
#pragma unroll
            for (int i=0;i<16;i+=2){ a0 = fmaf(kf[i], s[i], a0); a1 = fmaf(kf[i+1], s[i+1], a1); }
            float dot = a0 + a1;
            dot += __shfl_xor_sync(0xffffffffu, dot, 1);
            dot += __shfl_xor_sync(0xffffffffu, dot, 2);
            dot += __shfl_xor_sync(0xffffffffu, dot, 4);
            float pred = dot * ksc * eg;
            float uk = bet * (vv - pred) * ksc;
#pragma unroll
            for (int i=0;i<16;i++) s[i] = fmaf(eg, s[i], kf[i]*uk);
            float c0=0.f, c1=0.f;
#pragma unroll
            for (int i=0;i<16;i+=2){ c0 = fmaf(qf[i], s[i], c0); c1 = fmaf(qf[i+1], s[i+1], c1); }
            float od = c0 + c1;
            od += __shfl_xor_sync(0xffffffffu, od, 1);
            od += __shfl_xor_sync(0xffffffffu, od, 2);
            od += __shfl_xor_sync(0xffffffffu, od, 4);
            if (kg == 0){
                int t = c*CH + j;
                o[(size_t)t*(NH*128) + h*128 + v] = od * qsc;
            }
        }
        __syncthreads();
    }
}

// ---------------- launch ----------------------------------------------------
#define DSMEM_128 (3*(16384 + 128*128))   // 98304
#define DSMEM_64  (3*(16384 + 64*128))    // 73728

extern "C" void kernel_launch(void* const* d_in, const int* in_sizes, int n_in,
                              void* d_out, int out_size)
{
    const float* x      = (const float*)d_in[0];
    const float* W_qkv  = (const float*)d_in[1];
    const float* W_ba   = (const float*)d_in[2];
    const float* gen_w1 = (const float*)d_in[3];
    const float* gen_w2 = (const float*)d_in[4];
    const float* gen_b2 = (const float*)d_in[5];
    const float* W_o    = (const float*)d_in[6];
    float* y = (float*)d_out;

    float *qkv, *u, *o, *beta, *decay, *qs, *ks;
    cudaGetSymbolAddress((void**)&qkv,   g_qkv);
    cudaGetSymbolAddress((void**)&u,     g_u);
    cudaGetSymbolAddress((void**)&o,     g_o);
    cudaGetSymbolAddress((void**)&beta,  g_beta);
    cudaGetSymbolAddress((void**)&decay, g_decay);
    cudaGetSymbolAddress((void**)&qs,    g_qs);
    cudaGetSymbolAddress((void**)&ks,    g_ks);
    __nv_bfloat16 *xh,*xl,*qkvh,*qkvl,*hh,*hl,*oh,*ol;
    __nv_bfloat16 *wqkvh,*wqkvl,*w1h,*w1l,*w2h,*w2l,*woh,*wol;
    cudaGetSymbolAddress((void**)&xh, g_xh);     cudaGetSymbolAddress((void**)&xl, g_xl);
    cudaGetSymbolAddress((void**)&qkvh, g_qkvh); cudaGetSymbolAddress((void**)&qkvl, g_qkvl);
    cudaGetSymbolAddress((void**)&hh, g_hh);     cudaGetSymbolAddress((void**)&hl, g_hl);
    cudaGetSymbolAddress((void**)&oh, g_oh);     cudaGetSymbolAddress((void**)&ol, g_ol);
    cudaGetSymbolAddress((void**)&wqkvh, g_wqkvh); cudaGetSymbolAddress((void**)&wqkvl, g_wqkvl);
    cudaGetSymbolAddress((void**)&w1h, g_w1h);   cudaGetSymbolAddress((void**)&w1l, g_w1l);
    cudaGetSymbolAddress((void**)&w2h, g_w2h);   cudaGetSymbolAddress((void**)&w2l, g_w2l);
    cudaGetSymbolAddress((void**)&woh, g_woh);   cudaGetSymbolAddress((void**)&wol, g_wol);

    cudaFuncSetAttribute((const void*)mma_gemm<0,128>, cudaFuncAttributeMaxDynamicSharedMemorySize, DSMEM_128);
    cudaFuncSetAttribute((const void*)mma_gemm<1,128>, cudaFuncAttributeMaxDynamicSharedMemorySize, DSMEM_128);
    cudaFuncSetAttribute((const void*)mma_gemm<2,64>,  cudaFuncAttributeMaxDynamicSharedMemorySize, DSMEM_64);
    cudaFuncSetAttribute((const void*)mma_gemm<3,128>, cudaFuncAttributeMaxDynamicSharedMemorySize, DSMEM_128);

    // weight transpose+split  ([K,N] fp32 -> [N,K] bf16 hi/lo)
    transpose_split_kernel<<<dim3(CONV_DIM/32, D_MODEL/32), 256>>>(W_qkv, wqkvh, wqkvl, D_MODEL, CONV_DIM);
    transpose_split_kernel<<<dim3(GEN_HIDDEN/32, CONV_DIM/32), 256>>>(gen_w1, w1h, w1l, CONV_DIM, GEN_HIDDEN);
    transpose_split_kernel<<<dim3(KERN_N/32, GEN_HIDDEN/32), 256>>>(gen_w2, w2h, w2l, GEN_HIDDEN, KERN_N);
    transpose_split_kernel<<<dim3(D_MODEL/32, D_MODEL/32), 256>>>(W_o, woh, wol, D_MODEL, D_MODEL);
    // x split
    split4_kernel<<<(T_SEQ*D_MODEL)/1024, 256>>>(x, xh, xl);
    // beta / decay
    ba_kernel<<<T_SEQ/8, 256>>>(x, W_ba, beta, decay);

    // 1) qkv = x @ W_qkv  (fp32 + bf16 split outputs)
    mma_gemm<1,128><<<dim3(CONV_DIM/128, T_SEQ/128), 256, DSMEM_128>>>(
        xh, xl, wqkvh, wqkvl, CONV_DIM, D_MODEL, qkv, qkvh, qkvl, nullptr, nullptr);
    // 2) h = silu(qkv @ gen_w1)  (bf16 split only; BN=64 for occupancy: 192 blocks)
    mma_gemm<2,64><<<dim3(GEN_HIDDEN/64, T_SEQ/128), 256, DSMEM_64>>>(
        qkvh, qkvl, w1h, w1l, GEN_HIDDEN, CONV_DIM, nullptr, hh, hl, nullptr, nullptr);
    // 3) u = silu(conv(qkv, h @ gen_w2 + b2))  (fused conv epilogue)
    mma_gemm<3,128><<<dim3(KERN_N/128, T_SEQ/128), 256, DSMEM_128>>>(
        hh, hl, w2h, w2l, KERN_N, GEN_HIDDEN, u, nullptr, nullptr, qkv, gen_b2);
    // 4) scales + scan
    scale_kernel<<<(T_SEQ*NH*32)/256, 256>>>(u, qs, ks);
    scan_kernel<<<dim3(8, NH), 128>>>(u, ks, qs, beta, decay, o);
    // 5) o split + y = o @ W_o
    split4_kernel<<<(T_SEQ*D_MODEL)/1024, 256>>>(o, oh, ol);
    mma_gemm<0,128><<<dim3(D_MODEL/128, T_SEQ/128), 256, DSMEM_128>>>(
        oh, ol, woh, wol, D_MODEL, D_MODEL, y, nullptr, nullptr, nullptr, nullptr);
}